// round 17
// baseline (speedup 1.0000x reference)
#include <cuda_runtime.h>
#include <cstdint>
#include <cuda_fp16.h>

#define N_NODES 30000
#define N_EDGES 480000
#define IN_FEAT 256
#define OUT_FEAT 256
#define N_RELS 8
#define N_HEADS 4
#define HEAD_DIM 64
#define CAP 64                      // max in-degree bin (Poisson(16): P(>=64) ~ 1e-18)
#define BK 64
#define NKT 4                       // 256 / 64 K-tiles
#define WPR 32                      // words per row (BK/2)
#define STR 36                      // smem row stride in words (WPR + 4 pad)

// -------- scratch (static device globals; no allocations allowed) --------
__device__ uint32_t g_feat[(size_t)N_RELS * N_NODES * 128];     // f16x2: [r][n][word]
__device__ float g_el[N_RELS * N_NODES * N_HEADS];              // [r][n][h]
__device__ float g_er[N_RELS * N_NODES * N_HEADS];
__device__ int   g_counts[N_NODES];                             // BSS-zeroed; re-zeroed by agg
__device__ int   g_perm[(size_t)N_NODES * CAP];

// pack two f32 into f16x2: low half = lo, high half = hi
__device__ __forceinline__ uint32_t pack_h2(float lo, float hi) {
    uint32_t u;
    asm("cvt.rn.f16x2.f32 %0, %1, %2;" : "=r"(u) : "f"(hi), "f"(lo));
    return u;
}

// mma m16n8k16 f16 inputs, f32 accumulate
__device__ __forceinline__ void mma_f16(float c[4], const uint32_t a[4], const uint32_t b[2]) {
    asm volatile(
        "mma.sync.aligned.m16n8k16.row.col.f32.f16.f16.f32 "
        "{%0,%1,%2,%3}, {%4,%5,%6,%7}, {%8,%9}, {%0,%1,%2,%3};"
        : "+f"(c[0]), "+f"(c[1]), "+f"(c[2]), "+f"(c[3])
        : "r"(a[0]), "r"(a[1]), "r"(a[2]), "r"(a[3]), "r"(b[0]), "r"(b[1]));
}

#define LDSM4(r0, r1, r2, r3, addr)                                           \
    asm volatile("ldmatrix.sync.aligned.m8n8.x4.shared.b16 {%0,%1,%2,%3}, [%4];" \
                 : "=r"(r0), "=r"(r1), "=r"(r2), "=r"(r3) : "r"(addr))

__device__ __forceinline__ float lrelu(float x) { return x >= 0.f ? x : 0.2f * x; }

// ---------------------------------------------------------------------------
// Kernel 1: GEMM  C[128 x 128] per CTA  (rowblock, rel*headpair)
//   feat_all[r][n][h*64+d] = sum_i inputs[n][i] * W[r][h][i][d]
// fp16 mma.sync m16n8k16 + ldmatrix (validated R13/R15 fragment mapping).
// BK=64: 4 K-tiles, HALF the barriers of R15. f32->f16x2 packed AT LOAD
// (cvt overlapped with mma; commit = pure STS). smem stride 36 words:
// ldmatrix rows hit banks 4r mod 32 -> conflict-free.
// ---------------------------------------------------------------------------
__global__ __launch_bounds__(256, 2) void gemm_kernel(
    const float* __restrict__ A,        // [N_NODES, 256]
    const float* __restrict__ W,        // [8,4,256,64]
    const float* __restrict__ attn_l,   // [8,4,64]
    const float* __restrict__ attn_r)   // [8,4,64]
{
    __shared__ uint32_t sAh[128 * STR]; // [row][w]: w = k/2
    __shared__ uint32_t sBh[128 * STR]; // [n][w]:   w = k/2

    const int r  = blockIdx.y >> 1;
    const int hp = blockIdx.y & 1;      // head pair: heads {2hp, 2hp+1}
    const int rowBase = blockIdx.x * 128;
    const int tid = threadIdx.x;
    const int warp = tid >> 5, lane = tid & 31;
    const int warp_m = warp >> 1;       // 0..3 (row group of 32)
    const int warp_n = warp & 1;        // 0..1 (head within pair)
    const int g = lane >> 2, t = lane & 3;
    const int cb = warp_n * 64;         // B row (col) base within 128-wide tile

    const float* Wbase = W + (size_t)(r * 4 + hp * 2) * IN_FEAT * HEAD_DIM;

    float c[2][8][4];
#pragma unroll
    for (int m = 0; m < 2; m++)
#pragma unroll
        for (int j = 0; j < 8; j++)
#pragma unroll
            for (int q = 0; q < 4; q++) c[m][j][q] = 0.f;

    // staging registers (packed f16x2) for the next K-tile
    uint2    arp[8];                    // A: 8 float4 -> 8 uint2
    uint32_t brp[16];                   // B: 16 packed words

    // B loader: thread owns n-row (tid&127); half (tid>>7) selects words 0-15/16-31
    const int bn = tid & 127, bhalf = tid >> 7;
    const float* wcol = Wbase + (size_t)(bn >> 6) * (IN_FEAT * HEAD_DIM) + (bn & 63);

    auto ldA = [&](int k0) {
#pragma unroll
        for (int i = 0; i < 8; i++) {
            int idx = tid + i * 256;
            int row = idx >> 4, c4 = (idx & 15) << 2;
            int gr = rowBase + row;
            float4 v = (gr < N_NODES)
                     ? *(const float4*)(A + (size_t)gr * IN_FEAT + k0 + c4)
                     : make_float4(0.f, 0.f, 0.f, 0.f);
            arp[i].x = pack_h2(v.x, v.y);
            arp[i].y = pack_h2(v.z, v.w);
        }
    };
    auto ldB = [&](int k0) {
#pragma unroll
        for (int w = 0; w < 16; w++) {
            int k = k0 + (bhalf * 16 + w) * 2;
            brp[w] = pack_h2(wcol[(size_t)k * HEAD_DIM],
                             wcol[(size_t)(k + 1) * HEAD_DIM]);
        }
    };
    auto commit = [&]() {
#pragma unroll
        for (int i = 0; i < 8; i++) {
            int idx = tid + i * 256;
            int row = idx >> 4, c4 = (idx & 15) << 2;
            *(uint2*)&sAh[row * STR + (c4 >> 1)] = arp[i];
        }
#pragma unroll
        for (int w = 0; w < 16; w++)
            sBh[bn * STR + bhalf * 16 + w] = brp[w];
    };

    ldA(0); ldB(0);
    commit();
    __syncthreads();

    // per-lane ldmatrix addresses (bytes)
    uint32_t sA_b = (uint32_t)__cvta_generic_to_shared(sAh);
    uint32_t sB_b = (uint32_t)__cvta_generic_to_shared(sBh);
    uint32_t aAddr = sA_b + (((warp_m * 32 + (lane & 15)) * STR + ((lane >> 4) << 2)) << 2);
    uint32_t bAddr = sB_b + (((cb + ((lane >> 4) << 3) + (lane & 7)) * STR
                              + (((lane >> 3) & 1) << 2)) << 2);

#pragma unroll 1
    for (int tk = 0; tk < NKT; tk++) {
        const bool has_next = (tk + 1) < NKT;
        if (has_next) { ldA((tk + 1) * BK); ldB((tk + 1) * BK); }  // overlap with mma

#pragma unroll
        for (int ks = 0; ks < 4; ks++) {
            const uint32_t ko = (ks * 8) << 2;          // +8 words per ks
            uint32_t a[2][4], b[8][2];
            LDSM4(a[0][0], a[0][1], a[0][2], a[0][3], aAddr + ko);
            LDSM4(a[1][0], a[1][1], a[1][2], a[1][3], aAddr + ko + ((16 * STR) << 2));
#pragma unroll
            for (int j2 = 0; j2 < 4; j2++) {
                LDSM4(b[2 * j2][0], b[2 * j2][1], b[2 * j2 + 1][0], b[2 * j2 + 1][1],
                      bAddr + ko + ((16 * STR * j2) << 2));
            }
#pragma unroll
            for (int m = 0; m < 2; m++)
#pragma unroll
                for (int j = 0; j < 8; j++) mma_f16(c[m][j], a[m], b[j]);
        }
        __syncthreads();
        if (has_next) {
            commit();
            __syncthreads();
        }
    }

    // ---- epilogue: el/er dots from f32 accums, feat stored as f16x2 ----
    const int head = hp * 2 + warp_n;
    const int rh = r * 4 + head;
    const float* alp = attn_l + rh * HEAD_DIM;
    const float* arp2 = attn_r + rh * HEAD_DIM;

#pragma unroll
    for (int m = 0; m < 2; m++) {
        float pl0 = 0.f, pl1 = 0.f, pr0 = 0.f, pr1 = 0.f;
#pragma unroll
        for (int j = 0; j < 8; j++) {
            int col = j * 8 + 2 * t;
            float al0 = alp[col], al1 = alp[col + 1];
            float ar0 = arp2[col], ar1 = arp2[col + 1];
            pl0 += c[m][j][0] * al0 + c[m][j][1] * al1;
            pl1 += c[m][j][2] * al0 + c[m][j][3] * al1;
            pr0 += c[m][j][0] * ar0 + c[m][j][1] * ar1;
            pr1 += c[m][j][2] * ar0 + c[m][j][3] * ar1;
        }
        pl0 += __shfl_xor_sync(0xFFFFFFFFu, pl0, 1);
        pl0 += __shfl_xor_sync(0xFFFFFFFFu, pl0, 2);
        pl1 += __shfl_xor_sync(0xFFFFFFFFu, pl1, 1);
        pl1 += __shfl_xor_sync(0xFFFFFFFFu, pl1, 2);
        pr0 += __shfl_xor_sync(0xFFFFFFFFu, pr0, 1);
        pr0 += __shfl_xor_sync(0xFFFFFFFFu, pr0, 2);
        pr1 += __shfl_xor_sync(0xFFFFFFFFu, pr1, 1);
        pr1 += __shfl_xor_sync(0xFFFFFFFFu, pr1, 2);

        int row0 = rowBase + warp_m * 32 + m * 16 + g;
        int row1 = row0 + 8;
        if (t == 0) {
            if (row0 < N_NODES) {
                g_el[((size_t)r * N_NODES + row0) * 4 + head] = pl0;
                g_er[((size_t)r * N_NODES + row0) * 4 + head] = pr0;
            }
            if (row1 < N_NODES) {
                g_el[((size_t)r * N_NODES + row1) * 4 + head] = pl1;
                g_er[((size_t)r * N_NODES + row1) * 4 + head] = pr1;
            }
        }
#pragma unroll
        for (int j = 0; j < 8; j++) {
            int word = head * 32 + j * 4 + t;        // col/2, col = head*64+j*8+2t
            if (row0 < N_NODES)
                g_feat[((size_t)r * N_NODES + row0) * 128 + word] =
                    pack_h2(c[m][j][0], c[m][j][1]);
            if (row1 < N_NODES)
                g_feat[((size_t)r * N_NODES + row1) * 128 + word] =
                    pack_h2(c[m][j][2], c[m][j][3]);
        }
    }
}

// ---------------------------------------------------------------------------
// Kernel 2: fused bin scatter: each edge claims a slot in its destination's
// fixed-capacity bin via one atomic. (g_counts zeroed by the previous call's
// agg_kernel; BSS-zero on first call.)
// ---------------------------------------------------------------------------
__global__ void scatter_kernel(const int* __restrict__ edge_dst) {
    int i = blockIdx.x * blockDim.x + threadIdx.x;
    if (i < N_EDGES) {
        int d = edge_dst[i];
        int pos = atomicAdd(&g_counts[d], 1);
        if (pos < CAP) g_perm[(size_t)d * CAP + pos] = i;
    }
}

// ---------------------------------------------------------------------------
// Kernel 3: fused segment softmax + weighted aggregation. Warp per node.
// f16x2-packed feat rows: one uint4 gather per lane per edge; f32 accum.
// Also RE-ZEROES g_counts[node] for the next launch (replaces the memset).
// ---------------------------------------------------------------------------
__global__ __launch_bounds__(256) void agg_kernel(
    const int* __restrict__ edge_src,
    const int* __restrict__ edge_type,
    const float* __restrict__ h_bias,
    float* __restrict__ out)
{
    const int warp = threadIdx.x >> 5;
    const int lane = threadIdx.x & 31;
    const int node = blockIdx.x * 8 + warp;
    if (node >= N_NODES) return;

    const int cnt = min(g_counts[node], CAP);
    if (lane == 0) g_counts[node] = 0;       // reset for next launch
    const size_t base = (size_t)node * CAP;

    float s0 = 0.f, s1 = 0.f, s2 = 0.f, s3 = 0.f;
    float acc[8];
#pragma unroll
    for (int q = 0; q < 8; q++) acc[q] = 0.f;
    const int hsel = lane >> 3;              // head of this lane's 8 output columns

    for (int b0 = 0; b0 < cnt; b0 += 32) {
        int j = b0 + lane;
        float w0 = 0.f, w1 = 0.f, w2 = 0.f, w3 = 0.f;
        int src = 0, et = 0;
        if (j < cnt) {
            int eid = g_perm[base + j];
            et = edge_type[eid];
            src = edge_src[eid];
            float4 el = *(const float4*)&g_el[((size_t)et * N_NODES + src) * 4];
            float4 er = *(const float4*)&g_er[((size_t)et * N_NODES + node) * 4];
            w0 = __expf(lrelu(el.x + er.x));
            w1 = __expf(lrelu(el.y + er.y));
            w2 = __expf(lrelu(el.z + er.z));
            w3 = __expf(lrelu(el.w + er.w));
            s0 += w0; s1 += w1; s2 += w2; s3 += w3;
        }
        int c2 = min(32, cnt - b0);
        for (int tt = 0; tt < c2; tt++) {
            int bsrc = __shfl_sync(0xFFFFFFFFu, src, tt);
            int bet  = __shfl_sync(0xFFFFFFFFu, et, tt);
            float bw0 = __shfl_sync(0xFFFFFFFFu, w0, tt);
            float bw1 = __shfl_sync(0xFFFFFFFFu, w1, tt);
            float bw2 = __shfl_sync(0xFFFFFFFFu, w2, tt);
            float bw3 = __shfl_sync(0xFFFFFFFFu, w3, tt);
            float ww = (hsel == 0) ? bw0 : (hsel == 1) ? bw1 : (hsel == 2) ? bw2 : bw3;
            const uint4* fp =
                (const uint4*)&g_feat[((size_t)bet * N_NODES + bsrc) * 128 + lane * 4];
            uint4 v = *fp;
            float2 f0 = __half22float2(*(const __half2*)&v.x);
            float2 f1 = __half22float2(*(const __half2*)&v.y);
            float2 f2 = __half22float2(*(const __half2*)&v.z);
            float2 f3 = __half22float2(*(const __half2*)&v.w);
            acc[0] += ww * f0.x; acc[1] += ww * f0.y;
            acc[2] += ww * f1.x; acc[3] += ww * f1.y;
            acc[4] += ww * f2.x; acc[5] += ww * f2.y;
            acc[6] += ww * f3.x; acc[7] += ww * f3.y;
        }
    }
#pragma unroll
    for (int off = 16; off >= 1; off >>= 1) {
        s0 += __shfl_xor_sync(0xFFFFFFFFu, s0, off);
        s1 += __shfl_xor_sync(0xFFFFFFFFu, s1, off);
        s2 += __shfl_xor_sync(0xFFFFFFFFu, s2, off);
        s3 += __shfl_xor_sync(0xFFFFFFFFu, s3, off);
    }
    float sh = (hsel == 0) ? s0 : (hsel == 1) ? s1 : (hsel == 2) ? s2 : s3;
    float inv = (cnt > 0) ? (1.f / sh) : 0.f;

    int col = lane * 8;
    float4 o0, o1;
    o0.x = acc[0] * inv + h_bias[col + 0];
    o0.y = acc[1] * inv + h_bias[col + 1];
    o0.z = acc[2] * inv + h_bias[col + 2];
    o0.w = acc[3] * inv + h_bias[col + 3];
    o1.x = acc[4] * inv + h_bias[col + 4];
    o1.y = acc[5] * inv + h_bias[col + 5];
    o1.z = acc[6] * inv + h_bias[col + 6];
    o1.w = acc[7] * inv + h_bias[col + 7];
    *(float4*)&out[(size_t)node * 256 + col] = o0;
    *(float4*)&out[(size_t)node * 256 + col + 4] = o1;
}

// ---------------------------------------------------------------------------
extern "C" void kernel_launch(void* const* d_in, const int* in_sizes, int n_in,
                              void* d_out, int out_size) {
    const float* inputs  = (const float*)d_in[0];
    const float* conv_w  = (const float*)d_in[1];
    const float* attn_l  = (const float*)d_in[2];
    const float* attn_r  = (const float*)d_in[3];
    const float* h_bias  = (const float*)d_in[4];
    const int*   e_src   = (const int*)d_in[5];
    const int*   e_dst   = (const int*)d_in[6];
    const int*   e_type  = (const int*)d_in[7];
    float* out = (float*)d_out;

    gemm_kernel<<<dim3((N_NODES + 127) / 128, N_RELS * 2), 256>>>(
        inputs, conv_w, attn_l, attn_r);
    scatter_kernel<<<(N_EDGES + 255) / 256, 256>>>(e_dst);
    agg_kernel<<<(N_NODES + 7) / 8, 256>>>(e_src, e_type, h_bias, out);
}